// round 1
// baseline (speedup 1.0000x reference)
#include <cuda_runtime.h>
#include <math.h>

#define IMG    512
#define IMG2   (IMG * IMG)        // 262144 elements per image
#define NBATCH 16
#define NTEN   (NBATCH * IMG2)    // 4194304 per tensor
#define NTOT   (2 * NTEN)         // 8388608 both tensors
#define NITER  200
#define BMP_WORDS 131080          // ceil((NTEN+1)/32) = 131073, padded

// ---------------- device scratch (static, no allocation) ----------------
__device__ float    g_buf[2][NTOT];       // ping-pong label buffers (pred | target)
__device__ unsigned g_bmp[2][BMP_WORDS];  // uniqueness bitmaps
__device__ float    g_pnum[512];          // per (batch,chunk) partial sum p*t
__device__ float    g_pden[512];          // per (batch,chunk) partial sum p^2+t^2
__device__ int      g_maxbits[2];         // float-as-int global max of p, t (values >= 0)
__device__ int      g_cnt[2];             // unique counts

// ---------------- helpers ----------------
__device__ __forceinline__ float4 fmax4(float4 a, float4 b) {
    return make_float4(fmaxf(a.x, b.x), fmaxf(a.y, b.y),
                       fmaxf(a.z, b.z), fmaxf(a.w, b.w));
}

// ---------------- init: clear scratch ----------------
__global__ void init_kernel() {
    int i = blockIdx.x * blockDim.x + threadIdx.x;
    int stride = gridDim.x * blockDim.x;
    for (int w = i; w < BMP_WORDS; w += stride) {
        g_bmp[0][w] = 0u;
        g_bmp[1][w] = 0u;
    }
    if (i < 512) { g_pnum[i] = 0.f; g_pden[i] = 0.f; }
    if (i < 2)   { g_maxbits[i] = 0; g_cnt[i] = 0; }
}

// ---------------- pass 1: dice partial sums + global maxes ----------------
// grid (32 chunks, 16 batches), 256 threads; each block covers 8192 elements.
__global__ void __launch_bounds__(256) reduce_kernel(const float* __restrict__ p,
                                                     const float* __restrict__ t) {
    const int b = blockIdx.y, c = blockIdx.x, tid = threadIdx.x;
    const float4* p4 = reinterpret_cast<const float4*>(p + (size_t)b * IMG2) + c * 2048;
    const float4* t4 = reinterpret_cast<const float4*>(t + (size_t)b * IMG2) + c * 2048;
    float s1 = 0.f, s2 = 0.f, mp = 0.f, mt = 0.f;
#pragma unroll
    for (int k = 0; k < 8; k++) {
        float4 a = p4[k * 256 + tid];
        float4 d = t4[k * 256 + tid];
        s1 += a.x * d.x + a.y * d.y + a.z * d.z + a.w * d.w;
        s2 += a.x * a.x + a.y * a.y + a.z * a.z + a.w * a.w;
        s2 += d.x * d.x + d.y * d.y + d.z * d.z + d.w * d.w;
        mp = fmaxf(mp, fmaxf(fmaxf(a.x, a.y), fmaxf(a.z, a.w)));
        mt = fmaxf(mt, fmaxf(fmaxf(d.x, d.y), fmaxf(d.z, d.w)));
    }
#pragma unroll
    for (int o = 16; o; o >>= 1) {
        s1 += __shfl_down_sync(0xffffffffu, s1, o);
        s2 += __shfl_down_sync(0xffffffffu, s2, o);
        mp = fmaxf(mp, __shfl_down_sync(0xffffffffu, mp, o));
        mt = fmaxf(mt, __shfl_down_sync(0xffffffffu, mt, o));
    }
    __shared__ float sh1[8], sh2[8], shm[8], sht[8];
    if ((tid & 31) == 0) {
        int w = tid >> 5;
        sh1[w] = s1; sh2[w] = s2; shm[w] = mp; sht[w] = mt;
    }
    __syncthreads();
    if (tid == 0) {
        float a1 = sh1[0], a2 = sh2[0], m1 = shm[0], m2 = sht[0];
        for (int w = 1; w < 8; w++) {
            a1 += sh1[w]; a2 += sh2[w];
            m1 = fmaxf(m1, shm[w]); m2 = fmaxf(m2, sht[w]);
        }
        g_pnum[b * 32 + c] = a1;
        g_pden[b * 32 + c] = a2;
        atomicMax(&g_maxbits[0], __float_as_int(m1));  // values >= 0: int order == float order
        atomicMax(&g_maxbits[1], __float_as_int(m2));
    }
}

// ---------------- pass 2: build seed arrays ----------------
// seed = (v > max/2) ? (local_idx + 1) : 0, exact in fp32 (idx+1 < 2^23)
__global__ void __launch_bounds__(256) seed_kernel(const float* __restrict__ p,
                                                   const float* __restrict__ t) {
    int i = blockIdx.x * blockDim.x + threadIdx.x;   // float4 index, < NTEN/4
    float thp = 0.5f * __int_as_float(g_maxbits[0]);
    float tht = 0.5f * __int_as_float(g_maxbits[1]);
    int base = 4 * i;
    float4 a = reinterpret_cast<const float4*>(p)[i];
    float4 s;
    s.x = (a.x > thp) ? (float)(base + 1) : 0.f;
    s.y = (a.y > thp) ? (float)(base + 2) : 0.f;
    s.z = (a.z > thp) ? (float)(base + 3) : 0.f;
    s.w = (a.w > thp) ? (float)(base + 4) : 0.f;
    reinterpret_cast<float4*>(g_buf[0])[i] = s;
    float4 d = reinterpret_cast<const float4*>(t)[i];
    s.x = (d.x > tht) ? (float)(base + 1) : 0.f;
    s.y = (d.y > tht) ? (float)(base + 2) : 0.f;
    s.z = (d.z > tht) ? (float)(base + 3) : 0.f;
    s.w = (d.w > tht) ? (float)(base + 4) : 0.f;
    reinterpret_cast<float4*>(g_buf[0] + NTEN)[i] = s;
}

// ---------------- propagation: one masked 3x3 max-pool iteration ----------------
// Invariant: mask == (cur > 0). new = (cur > 0) ? max3x3(cur) : 0.
// Thread = one float4 column group x 8 rows (register-rolling vertical max).
// grid (4, 16, 32 images), block (32, 4).
__device__ __forceinline__ void load_row(const float* __restrict__ base, int r, int j,
                                         float4& b, float& a, float& c) {
    if ((unsigned)r < (unsigned)IMG) {
        b = *reinterpret_cast<const float4*>(base + r * IMG + 4 * j);
        a = (j > 0)   ? __ldg(base + r * IMG + 4 * j - 1) : 0.f;
        c = (j < 127) ? __ldg(base + r * IMG + 4 * j + 4) : 0.f;
    } else {
        b = make_float4(0.f, 0.f, 0.f, 0.f); a = 0.f; c = 0.f;
    }
}

__global__ void __launch_bounds__(128) prop_kernel(int flip) {
    const float* __restrict__ in  = g_buf[flip];
    float* __restrict__ out = g_buf[flip ^ 1];
    const int img = blockIdx.z;
    const int j   = blockIdx.x * 32 + threadIdx.x;          // float4 column 0..127
    const int y0  = (blockIdx.y * 4 + threadIdx.y) * 8;     // first of 8 output rows
    const float* base  = in  + (size_t)img * IMG2;
    float*       obase = out + (size_t)img * IMG2;

    float4 p_b, cur_b, n_b, pm_b;
    float  p_a, p_c, cur_a, cur_c, n_a, n_c, pm_a, pm_c;

    load_row(base, y0 - 1, j, p_b, p_a, p_c);
    load_row(base, y0,     j, cur_b, cur_a, cur_c);
    pm_b = fmax4(p_b, cur_b);
    pm_a = fmaxf(p_a, cur_a);
    pm_c = fmaxf(p_c, cur_c);

#pragma unroll
    for (int r = 0; r < 8; ++r) {
        const int row = y0 + r;
        load_row(base, row + 1, j, n_b, n_a, n_c);
        float4 vb = fmax4(pm_b, n_b);          // vertical max rows r-1..r+1
        float  va = fmaxf(pm_a, n_a);          // only left-neighbor lane needed
        float  vc = fmaxf(pm_c, n_c);          // only right-neighbor lane needed
        float4 h;
        h.x = fmaxf(fmaxf(va,   vb.x), vb.y);
        h.y = fmaxf(fmaxf(vb.x, vb.y), vb.z);
        h.z = fmaxf(fmaxf(vb.y, vb.z), vb.w);
        h.w = fmaxf(fmaxf(vb.z, vb.w), vc);
        float4 o;
        o.x = (cur_b.x > 0.f) ? h.x : 0.f;
        o.y = (cur_b.y > 0.f) ? h.y : 0.f;
        o.z = (cur_b.z > 0.f) ? h.z : 0.f;
        o.w = (cur_b.w > 0.f) ? h.w : 0.f;
        *reinterpret_cast<float4*>(obase + row * IMG + 4 * j) = o;
        pm_b = fmax4(cur_b, n_b);
        pm_a = fmaxf(cur_a, n_a);
        pm_c = fmaxf(cur_c, n_c);
        cur_b = n_b; cur_a = n_a; cur_c = n_c;
    }
}

// ---------------- uniqueness: bitmap scatter ----------------
__global__ void __launch_bounds__(256) scatter_kernel() {
    int i = blockIdx.x * blockDim.x + threadIdx.x;   // float4 index, < NTOT/4
    float4 v = reinterpret_cast<const float4*>(g_buf[0])[i];
    unsigned* bmp = (i < (NTEN / 4)) ? g_bmp[0] : g_bmp[1];
    unsigned id0 = (unsigned)v.x, id1 = (unsigned)v.y;
    unsigned id2 = (unsigned)v.z, id3 = (unsigned)v.w;
    unsigned ids[4] = {id0, id1, id2, id3};
    unsigned prev = 0xffffffffu;
#pragma unroll
    for (int k = 0; k < 4; k++) {
        unsigned id = ids[k];
        if (id == prev) continue;                 // spatial dedup (labels cluster)
        prev = id;
        unsigned w = id >> 5, m = 1u << (id & 31);
        if (!(bmp[w] & m)) atomicOr(&bmp[w], m);  // test first: idempotent, kills hot-word storms
    }
}

__global__ void __launch_bounds__(256) popcnt_kernel() {
    int which = blockIdx.y;
    int i = blockIdx.x * blockDim.x + threadIdx.x;
    int stride = gridDim.x * blockDim.x;
    int s = 0;
    for (int w = i; w < BMP_WORDS; w += stride) s += __popc(g_bmp[which][w]);
#pragma unroll
    for (int o = 16; o; o >>= 1) s += __shfl_down_sync(0xffffffffu, s, o);
    __shared__ int sh[8];
    if ((threadIdx.x & 31) == 0) sh[threadIdx.x >> 5] = s;
    __syncthreads();
    if (threadIdx.x == 0) {
        int tot = 0;
        for (int w = 0; w < 8; w++) tot += sh[w];
        atomicAdd(&g_cnt[which], tot);
    }
}

// ---------------- epilogue ----------------
__global__ void final_kernel(float* __restrict__ out) {
    float acc = 0.f;
    for (int b = 0; b < NBATCH; b++) {
        float num = 0.f, den = 0.f;
        for (int c = 0; c < 32; c++) { num += g_pnum[b * 32 + c]; den += g_pden[b * 32 + c]; }
        acc += 1.0f - (num + 1.0f) / (den + 1.0f);
    }
    float nl = (float)(g_cnt[0] - 1);   // count_unique(labels) - 1
    float nt = (float)g_cnt[1];         // count_unique(target_number)  (no -1, per reference)
    float pen = sqrtf(nl / nt);
    if (!isfinite(pen)) pen = (float)NBATCH;
    pen = fminf(fmaxf(pen, 1.0f), (float)NBATCH);
    out[0] = (acc / (float)NBATCH) * pen;
}

// ---------------- launch ----------------
extern "C" void kernel_launch(void* const* d_in, const int* in_sizes, int n_in,
                              void* d_out, int out_size) {
    const float* p = (const float*)d_in[0];
    const float* t = (const float*)d_in[1];
    float* out = (float*)d_out;

    init_kernel<<<512, 256>>>();

    dim3 rgrid(32, 16);
    reduce_kernel<<<rgrid, 256>>>(p, t);

    seed_kernel<<<NTEN / 4 / 256, 256>>>(p, t);

    dim3 pblock(32, 4);
    dim3 pgrid(4, 16, 32);   // 4 x-tiles, 16 y-tiles, 32 images (16 pred + 16 target)
    for (int it = 0; it < NITER; ++it)
        prop_kernel<<<pgrid, pblock>>>(it & 1);   // 200 iters -> result back in g_buf[0]

    scatter_kernel<<<NTOT / 4 / 256, 256>>>();

    dim3 cgrid(64, 2);
    popcnt_kernel<<<cgrid, 256>>>();

    final_kernel<<<1, 1>>>(out);
}

// round 2
// speedup vs baseline: 1.8110x; 1.8110x over previous
#include <cuda_runtime.h>
#include <math.h>

#define IMG    512
#define IMG2   (IMG * IMG)        // 262144 elements per image
#define NBATCH 16
#define NTEN   (NBATCH * IMG2)    // 4194304 per tensor
#define NTOT   (2 * NTEN)         // 8388608 both tensors
#define BMP_WORDS 131080          // ceil((NTEN+1)/32) = 131073, padded
#define FULLMASK 0xffffffffu

// ---------------- device scratch (static, no allocation) ----------------
__device__ float    g_buf[2][NTOT];       // ping-pong label buffers (pred | target)
__device__ unsigned g_bmp[2][BMP_WORDS];  // uniqueness bitmaps
__device__ float    g_pnum[512];          // per (batch,chunk) partial sum p*t
__device__ float    g_pden[512];          // per (batch,chunk) partial sum p^2+t^2
__device__ int      g_maxbits[2];         // float-as-int global max of p, t (values >= 0)
__device__ int      g_cnt[2];             // unique counts

// ---------------- helpers ----------------
__device__ __forceinline__ float4 fmax4(float4 a, float4 b) {
    return make_float4(fmaxf(a.x, b.x), fmaxf(a.y, b.y),
                       fmaxf(a.z, b.z), fmaxf(a.w, b.w));
}
__device__ __forceinline__ float4 fmax4_3(float4 a, float4 b, float4 c) {
    return fmax4(a, fmax4(b, c));
}

// ---------------- init: clear scratch ----------------
__global__ void init_kernel() {
    int i = blockIdx.x * blockDim.x + threadIdx.x;
    int stride = gridDim.x * blockDim.x;
    for (int w = i; w < BMP_WORDS; w += stride) {
        g_bmp[0][w] = 0u;
        g_bmp[1][w] = 0u;
    }
    if (i < 512) { g_pnum[i] = 0.f; g_pden[i] = 0.f; }
    if (i < 2)   { g_maxbits[i] = 0; g_cnt[i] = 0; }
}

// ---------------- pass 1: dice partial sums + global maxes ----------------
__global__ void __launch_bounds__(256) reduce_kernel(const float* __restrict__ p,
                                                     const float* __restrict__ t) {
    const int b = blockIdx.y, c = blockIdx.x, tid = threadIdx.x;
    const float4* p4 = reinterpret_cast<const float4*>(p + (size_t)b * IMG2) + c * 2048;
    const float4* t4 = reinterpret_cast<const float4*>(t + (size_t)b * IMG2) + c * 2048;
    float s1 = 0.f, s2 = 0.f, mp = 0.f, mt = 0.f;
#pragma unroll
    for (int k = 0; k < 8; k++) {
        float4 a = p4[k * 256 + tid];
        float4 d = t4[k * 256 + tid];
        s1 += a.x * d.x + a.y * d.y + a.z * d.z + a.w * d.w;
        s2 += a.x * a.x + a.y * a.y + a.z * a.z + a.w * a.w;
        s2 += d.x * d.x + d.y * d.y + d.z * d.z + d.w * d.w;
        mp = fmaxf(mp, fmaxf(fmaxf(a.x, a.y), fmaxf(a.z, a.w)));
        mt = fmaxf(mt, fmaxf(fmaxf(d.x, d.y), fmaxf(d.z, d.w)));
    }
#pragma unroll
    for (int o = 16; o; o >>= 1) {
        s1 += __shfl_down_sync(FULLMASK, s1, o);
        s2 += __shfl_down_sync(FULLMASK, s2, o);
        mp = fmaxf(mp, __shfl_down_sync(FULLMASK, mp, o));
        mt = fmaxf(mt, __shfl_down_sync(FULLMASK, mt, o));
    }
    __shared__ float sh1[8], sh2[8], shm[8], sht[8];
    if ((tid & 31) == 0) {
        int w = tid >> 5;
        sh1[w] = s1; sh2[w] = s2; shm[w] = mp; sht[w] = mt;
    }
    __syncthreads();
    if (tid == 0) {
        float a1 = sh1[0], a2 = sh2[0], m1 = shm[0], m2 = sht[0];
        for (int w = 1; w < 8; w++) {
            a1 += sh1[w]; a2 += sh2[w];
            m1 = fmaxf(m1, shm[w]); m2 = fmaxf(m2, sht[w]);
        }
        g_pnum[b * 32 + c] = a1;
        g_pden[b * 32 + c] = a2;
        atomicMax(&g_maxbits[0], __float_as_int(m1));  // vals >= 0: int order == float order
        atomicMax(&g_maxbits[1], __float_as_int(m2));
    }
}

// ---------------- pass 2: build seed arrays ----------------
__global__ void __launch_bounds__(256) seed_kernel(const float* __restrict__ p,
                                                   const float* __restrict__ t) {
    int i = blockIdx.x * blockDim.x + threadIdx.x;   // float4 index, < NTEN/4
    float thp = 0.5f * __int_as_float(g_maxbits[0]);
    float tht = 0.5f * __int_as_float(g_maxbits[1]);
    int base = 4 * i;
    float4 a = reinterpret_cast<const float4*>(p)[i];
    float4 s;
    s.x = (a.x > thp) ? (float)(base + 1) : 0.f;
    s.y = (a.y > thp) ? (float)(base + 2) : 0.f;
    s.z = (a.z > thp) ? (float)(base + 3) : 0.f;
    s.w = (a.w > thp) ? (float)(base + 4) : 0.f;
    reinterpret_cast<float4*>(g_buf[0])[i] = s;
    float4 d = reinterpret_cast<const float4*>(t)[i];
    s.x = (d.x > tht) ? (float)(base + 1) : 0.f;
    s.y = (d.y > tht) ? (float)(base + 2) : 0.f;
    s.z = (d.z > tht) ? (float)(base + 3) : 0.f;
    s.w = (d.w > tht) ? (float)(base + 4) : 0.f;
    reinterpret_cast<float4*>(g_buf[0] + NTEN)[i] = s;
}

// ---------------- fused propagation: 8 masked 3x3 max-pool iterations ----------------
// Register-resident tile: in-tile 128x64 (always fully inside the image, via
// edge-clamped tile origins), out region = in-tile shrunk by margin 8 on sides
// interior to the image (margins touching the image border stay valid because
// the zero boundary condition is exact there).
// Layout: warp w (0..15) owns rows 4w..4w+3; lane l owns cols 4l..4l+3 (float4).
// Vertical halo rows exchanged via smem (1 syncthreads/iter, parity buffers),
// horizontal halo via warp shuffles. Mask invariant: mask == (val > 0).
__device__ __forceinline__ void hrow(float4& a, const float4 v, int l) {
    float vl = __shfl_up_sync(FULLMASK,  v.w, 1);
    float vr = __shfl_down_sync(FULLMASK, v.x, 1);
    if (l == 0)  vl = 0.f;   // outside tile: either true image edge (0) or garbage margin
    if (l == 31) vr = 0.f;
    float hx = fmaxf(vl,  fmaxf(v.x, v.y));
    float hy = fmaxf(v.x, fmaxf(v.y, v.z));
    float hz = fmaxf(v.y, fmaxf(v.z, v.w));
    float hw = fmaxf(fmaxf(v.z, v.w), vr);
    a.x = (a.x > 0.f) ? hx : 0.f;
    a.y = (a.y > 0.f) ? hy : 0.f;
    a.z = (a.z > 0.f) ? hz : 0.f;
    a.w = (a.w > 0.f) ? hw : 0.f;
}

__global__ void __launch_bounds__(512, 2) prop8_kernel(int src) {
    const float* __restrict__ in  = g_buf[src];
    float*       __restrict__ out = g_buf[src ^ 1];
    const int img = blockIdx.z;
    const int X0 = min((int)blockIdx.x * 112, 384);   // {0,112,224,336,384}
    const int Y0 = min((int)blockIdx.y * 48,  448);   // {0,48,...,432,448}
    const int w = threadIdx.x >> 5, l = threadIdx.x & 31;
    const int gx  = X0 + 4 * l;
    const int gy0 = Y0 + 4 * w;
    const float* base = in + (size_t)img * IMG2;

    // tile always fully inside the image: predicate-free coalesced loads
    float4 a0 = *reinterpret_cast<const float4*>(base + (gy0 + 0) * IMG + gx);
    float4 a1 = *reinterpret_cast<const float4*>(base + (gy0 + 1) * IMG + gx);
    float4 a2 = *reinterpret_cast<const float4*>(base + (gy0 + 2) * IMG + gx);
    float4 a3 = *reinterpret_cast<const float4*>(base + (gy0 + 3) * IMG + gx);

    __shared__ float4 shTop[2][16][32];   // warp w's row 4w
    __shared__ float4 shBot[2][16][32];   // warp w's row 4w+3
    const float4 z4 = make_float4(0.f, 0.f, 0.f, 0.f);

#pragma unroll
    for (int i = 0; i < 8; i++) {
        const int p = i & 1;
        shTop[p][w][l] = a0;
        shBot[p][w][l] = a3;
        __syncthreads();
        float4 aT = (w > 0)  ? shBot[p][w - 1][l] : z4;
        float4 aB = (w < 15) ? shTop[p][w + 1][l] : z4;
        float4 v0 = fmax4_3(aT, a0, a1);
        float4 v1 = fmax4_3(a0, a1, a2);
        float4 v2 = fmax4_3(a1, a2, a3);
        float4 v3 = fmax4_3(a2, a3, aB);
        hrow(a0, v0, l);
        hrow(a1, v1, l);
        hrow(a2, v2, l);
        hrow(a3, v3, l);
    }

    // store the valid (margin-8 or image-edge) region; overlapping tiles write
    // identical values (benign)
    const int vx0 = (X0 == 0)   ? 0   : X0 + 8;
    const int vx1 = (X0 == 384) ? 512 : X0 + 120;
    const int vy0 = (Y0 == 0)   ? 0   : Y0 + 8;
    const int vy1 = (Y0 == 448) ? 512 : Y0 + 56;
    float* obase = out + (size_t)img * IMG2;
    if (gx >= vx0 && gx < vx1) {
        if (gy0 + 0 >= vy0 && gy0 + 0 < vy1)
            *reinterpret_cast<float4*>(obase + (gy0 + 0) * IMG + gx) = a0;
        if (gy0 + 1 >= vy0 && gy0 + 1 < vy1)
            *reinterpret_cast<float4*>(obase + (gy0 + 1) * IMG + gx) = a1;
        if (gy0 + 2 >= vy0 && gy0 + 2 < vy1)
            *reinterpret_cast<float4*>(obase + (gy0 + 2) * IMG + gx) = a2;
        if (gy0 + 3 >= vy0 && gy0 + 3 < vy1)
            *reinterpret_cast<float4*>(obase + (gy0 + 3) * IMG + gx) = a3;
    }
}

// ---------------- uniqueness: bitmap scatter (reads g_buf[1]) ----------------
__global__ void __launch_bounds__(256) scatter_kernel() {
    int i = blockIdx.x * blockDim.x + threadIdx.x;   // float4 index, < NTOT/4
    float4 v = reinterpret_cast<const float4*>(g_buf[1])[i];
    unsigned* bmp = (i < (NTEN / 4)) ? g_bmp[0] : g_bmp[1];
    unsigned ids[4] = {(unsigned)v.x, (unsigned)v.y, (unsigned)v.z, (unsigned)v.w};
    unsigned prev = 0xffffffffu;
#pragma unroll
    for (int k = 0; k < 4; k++) {
        unsigned id = ids[k];
        if (id == prev) continue;                 // spatial dedup (labels cluster)
        prev = id;
        unsigned w = id >> 5, m = 1u << (id & 31);
        if (!(bmp[w] & m)) atomicOr(&bmp[w], m);  // test first: idempotent, kills hot-word storms
    }
}

__global__ void __launch_bounds__(256) popcnt_kernel() {
    int which = blockIdx.y;
    int i = blockIdx.x * blockDim.x + threadIdx.x;
    int stride = gridDim.x * blockDim.x;
    int s = 0;
    for (int w = i; w < BMP_WORDS; w += stride) s += __popc(g_bmp[which][w]);
#pragma unroll
    for (int o = 16; o; o >>= 1) s += __shfl_down_sync(FULLMASK, s, o);
    __shared__ int sh[8];
    if ((threadIdx.x & 31) == 0) sh[threadIdx.x >> 5] = s;
    __syncthreads();
    if (threadIdx.x == 0) {
        int tot = 0;
        for (int w = 0; w < 8; w++) tot += sh[w];
        atomicAdd(&g_cnt[which], tot);
    }
}

// ---------------- epilogue ----------------
__global__ void final_kernel(float* __restrict__ out) {
    float acc = 0.f;
    for (int b = 0; b < NBATCH; b++) {
        float num = 0.f, den = 0.f;
        for (int c = 0; c < 32; c++) { num += g_pnum[b * 32 + c]; den += g_pden[b * 32 + c]; }
        acc += 1.0f - (num + 1.0f) / (den + 1.0f);
    }
    float nl = (float)(g_cnt[0] - 1);   // count_unique(labels) - 1
    float nt = (float)g_cnt[1];         // count_unique(target_number)
    float pen = sqrtf(nl / nt);
    if (!isfinite(pen)) pen = (float)NBATCH;
    pen = fminf(fmaxf(pen, 1.0f), (float)NBATCH);
    out[0] = (acc / (float)NBATCH) * pen;
}

// ---------------- launch ----------------
extern "C" void kernel_launch(void* const* d_in, const int* in_sizes, int n_in,
                              void* d_out, int out_size) {
    const float* p = (const float*)d_in[0];
    const float* t = (const float*)d_in[1];
    float* out = (float*)d_out;

    init_kernel<<<512, 256>>>();

    dim3 rgrid(32, 16);
    reduce_kernel<<<rgrid, 256>>>(p, t);

    seed_kernel<<<NTEN / 4 / 256, 256>>>(p, t);

    // 25 launches x 8 fused iterations = 200; ping-pong g_buf[0] <-> g_buf[1]
    dim3 pgrid(5, 11, 32);
    for (int it = 0; it < 25; ++it)
        prop8_kernel<<<pgrid, 512>>>(it & 1);     // final result lands in g_buf[1]

    scatter_kernel<<<NTOT / 4 / 256, 256>>>();

    dim3 cgrid(64, 2);
    popcnt_kernel<<<cgrid, 256>>>();

    final_kernel<<<1, 1>>>(out);
}

// round 3
// speedup vs baseline: 2.2065x; 1.2184x over previous
#include <cuda_runtime.h>
#include <math.h>

#define IMG    512
#define IMG2   (IMG * IMG)        // 262144 elements per image
#define NBATCH 16
#define NTEN   (NBATCH * IMG2)    // 4194304 per tensor
#define NTOT   (2 * NTEN)         // 8388608 both tensors
#define BMP_WORDS 131080          // ceil((NTEN+1)/32) = 131073, padded
#define FULLMASK 0xffffffffu

// ---------------- device scratch (static, no allocation) ----------------
__device__ float    g_buf[2][NTOT];       // ping-pong label buffers (pred | target)
__device__ unsigned g_bmp[2][BMP_WORDS];  // uniqueness bitmaps
__device__ float    g_pnum[512];          // per (batch,chunk) partial sum p*t
__device__ float    g_pden[512];          // per (batch,chunk) partial sum p^2+t^2
__device__ int      g_maxbits[2];         // float-as-int global max of p, t (values >= 0)
__device__ int      g_cnt[2];             // unique counts

// ---------------- helpers ----------------
__device__ __forceinline__ float4 fmax4(float4 a, float4 b) {
    return make_float4(fmaxf(a.x, b.x), fmaxf(a.y, b.y),
                       fmaxf(a.z, b.z), fmaxf(a.w, b.w));
}

// ---------------- init: clear scratch ----------------
__global__ void init_kernel() {
    int i = blockIdx.x * blockDim.x + threadIdx.x;
    int stride = gridDim.x * blockDim.x;
    for (int w = i; w < BMP_WORDS; w += stride) {
        g_bmp[0][w] = 0u;
        g_bmp[1][w] = 0u;
    }
    if (i < 512) { g_pnum[i] = 0.f; g_pden[i] = 0.f; }
    if (i < 2)   { g_maxbits[i] = 0; g_cnt[i] = 0; }
}

// ---------------- pass 1: dice partial sums + global maxes ----------------
__global__ void __launch_bounds__(256) reduce_kernel(const float* __restrict__ p,
                                                     const float* __restrict__ t) {
    const int b = blockIdx.y, c = blockIdx.x, tid = threadIdx.x;
    const float4* p4 = reinterpret_cast<const float4*>(p + (size_t)b * IMG2) + c * 2048;
    const float4* t4 = reinterpret_cast<const float4*>(t + (size_t)b * IMG2) + c * 2048;
    float s1 = 0.f, s2 = 0.f, mp = 0.f, mt = 0.f;
#pragma unroll
    for (int k = 0; k < 8; k++) {
        float4 a = p4[k * 256 + tid];
        float4 d = t4[k * 256 + tid];
        s1 += a.x * d.x + a.y * d.y + a.z * d.z + a.w * d.w;
        s2 += a.x * a.x + a.y * a.y + a.z * a.z + a.w * a.w;
        s2 += d.x * d.x + d.y * d.y + d.z * d.z + d.w * d.w;
        mp = fmaxf(mp, fmaxf(fmaxf(a.x, a.y), fmaxf(a.z, a.w)));
        mt = fmaxf(mt, fmaxf(fmaxf(d.x, d.y), fmaxf(d.z, d.w)));
    }
#pragma unroll
    for (int o = 16; o; o >>= 1) {
        s1 += __shfl_down_sync(FULLMASK, s1, o);
        s2 += __shfl_down_sync(FULLMASK, s2, o);
        mp = fmaxf(mp, __shfl_down_sync(FULLMASK, mp, o));
        mt = fmaxf(mt, __shfl_down_sync(FULLMASK, mt, o));
    }
    __shared__ float sh1[8], sh2[8], shm[8], sht[8];
    if ((tid & 31) == 0) {
        int w = tid >> 5;
        sh1[w] = s1; sh2[w] = s2; shm[w] = mp; sht[w] = mt;
    }
    __syncthreads();
    if (tid == 0) {
        float a1 = sh1[0], a2 = sh2[0], m1 = shm[0], m2 = sht[0];
        for (int w = 1; w < 8; w++) {
            a1 += sh1[w]; a2 += sh2[w];
            m1 = fmaxf(m1, shm[w]); m2 = fmaxf(m2, sht[w]);
        }
        g_pnum[b * 32 + c] = a1;
        g_pden[b * 32 + c] = a2;
        atomicMax(&g_maxbits[0], __float_as_int(m1));  // vals >= 0: int order == float order
        atomicMax(&g_maxbits[1], __float_as_int(m2));
    }
}

// ---------------- pass 2: build seed arrays ----------------
__global__ void __launch_bounds__(256) seed_kernel(const float* __restrict__ p,
                                                   const float* __restrict__ t) {
    int i = blockIdx.x * blockDim.x + threadIdx.x;   // float4 index, < NTEN/4
    float thp = 0.5f * __int_as_float(g_maxbits[0]);
    float tht = 0.5f * __int_as_float(g_maxbits[1]);
    int base = 4 * i;
    float4 a = reinterpret_cast<const float4*>(p)[i];
    float4 s;
    s.x = (a.x > thp) ? (float)(base + 1) : 0.f;
    s.y = (a.y > thp) ? (float)(base + 2) : 0.f;
    s.z = (a.z > thp) ? (float)(base + 3) : 0.f;
    s.w = (a.w > thp) ? (float)(base + 4) : 0.f;
    reinterpret_cast<float4*>(g_buf[0])[i] = s;
    float4 d = reinterpret_cast<const float4*>(t)[i];
    s.x = (d.x > tht) ? (float)(base + 1) : 0.f;
    s.y = (d.y > tht) ? (float)(base + 2) : 0.f;
    s.z = (d.z > tht) ? (float)(base + 3) : 0.f;
    s.w = (d.w > tht) ? (float)(base + 4) : 0.f;
    reinterpret_cast<float4*>(g_buf[0] + NTEN)[i] = s;
}

// ---------------- fused propagation: 8 masked 3x3 max-pool iterations ----------------
// Register-resident tile 128x64 (edge-clamped origins keep it inside the image);
// valid output = tile shrunk by margin 8 on image-interior sides.
// Warp w (0..15) owns rows 4w..4w+3; lane l owns cols 4l..4l+3 (float4).
// Mask is invariant across the 8 fused iterations (masked pixels stay 0), so it
// is precomputed once as 0/1 floats and applied via FMUL on the (idle) FMA pipe.
// Vertical halo via smem (1 sync/iter, parity buffers); horizontal via shuffles.
__device__ __forceinline__ float4 hmask(const float4 v, const float4 m, int l) {
    float vl = __shfl_up_sync(FULLMASK,  v.w, 1);
    float vr = __shfl_down_sync(FULLMASK, v.x, 1);
    if (l == 0)  vl = 0.f;   // outside tile: true image edge (0) or garbage margin
    if (l == 31) vr = 0.f;
    float mxy = fmaxf(v.x, v.y);
    float myz = fmaxf(v.y, v.z);
    float mzw = fmaxf(v.z, v.w);
    float4 o;
    o.x = fmaxf(vl,  mxy) * m.x;   // mask multiply: exact for 0/1 masks, h >= 0
    o.y = fmaxf(mxy, v.z) * m.y;
    o.z = fmaxf(myz, v.w) * m.z;
    o.w = fmaxf(mzw, vr)  * m.w;
    return o;
}

__global__ void __launch_bounds__(512, 2) prop8_kernel(int src) {
    const float* __restrict__ in  = g_buf[src];
    float*       __restrict__ out = g_buf[src ^ 1];
    const int img = blockIdx.z;
    const int X0 = min((int)blockIdx.x * 112, 384);   // {0,112,224,336,384}
    const int Y0 = min((int)blockIdx.y * 48,  448);   // {0,48,...,432,448}
    const int w = threadIdx.x >> 5, l = threadIdx.x & 31;
    const int gx  = X0 + 4 * l;
    const int gy0 = Y0 + 4 * w;
    const float* base = in + (size_t)img * IMG2;

    float4 a0 = *reinterpret_cast<const float4*>(base + (gy0 + 0) * IMG + gx);
    float4 a1 = *reinterpret_cast<const float4*>(base + (gy0 + 1) * IMG + gx);
    float4 a2 = *reinterpret_cast<const float4*>(base + (gy0 + 2) * IMG + gx);
    float4 a3 = *reinterpret_cast<const float4*>(base + (gy0 + 3) * IMG + gx);

    // invariant 0/1 mask registers
    float4 m0 = make_float4(a0.x > 0.f ? 1.f : 0.f, a0.y > 0.f ? 1.f : 0.f,
                            a0.z > 0.f ? 1.f : 0.f, a0.w > 0.f ? 1.f : 0.f);
    float4 m1 = make_float4(a1.x > 0.f ? 1.f : 0.f, a1.y > 0.f ? 1.f : 0.f,
                            a1.z > 0.f ? 1.f : 0.f, a1.w > 0.f ? 1.f : 0.f);
    float4 m2 = make_float4(a2.x > 0.f ? 1.f : 0.f, a2.y > 0.f ? 1.f : 0.f,
                            a2.z > 0.f ? 1.f : 0.f, a2.w > 0.f ? 1.f : 0.f);
    float4 m3 = make_float4(a3.x > 0.f ? 1.f : 0.f, a3.y > 0.f ? 1.f : 0.f,
                            a3.z > 0.f ? 1.f : 0.f, a3.w > 0.f ? 1.f : 0.f);

    __shared__ float4 shTop[2][16][32];   // warp w's row 4w
    __shared__ float4 shBot[2][16][32];   // warp w's row 4w+3
    const float4 z4 = make_float4(0.f, 0.f, 0.f, 0.f);

#pragma unroll
    for (int i = 0; i < 8; i++) {
        const int p = i & 1;
        shTop[p][w][l] = a0;
        shBot[p][w][l] = a3;
        __syncthreads();
        float4 aT = (w > 0)  ? shBot[p][w - 1][l] : z4;
        float4 aB = (w < 15) ? shTop[p][w + 1][l] : z4;
        // vertical max with CSE
        float4 c01 = fmax4(a0, a1);
        float4 c12 = fmax4(a1, a2);
        float4 c23 = fmax4(a2, a3);
        float4 v0 = fmax4(aT,  c01);
        float4 v1 = fmax4(c01, a2);
        float4 v2 = fmax4(c12, a3);
        float4 v3 = fmax4(c23, aB);
        a0 = hmask(v0, m0, l);
        a1 = hmask(v1, m1, l);
        a2 = hmask(v2, m2, l);
        a3 = hmask(v3, m3, l);
    }

    // store valid (margin-8 or image-edge) region; overlap writes are identical
    const int vx0 = (X0 == 0)   ? 0   : X0 + 8;
    const int vx1 = (X0 == 384) ? 512 : X0 + 120;
    const int vy0 = (Y0 == 0)   ? 0   : Y0 + 8;
    const int vy1 = (Y0 == 448) ? 512 : Y0 + 56;
    float* obase = out + (size_t)img * IMG2;
    if (gx >= vx0 && gx < vx1) {
        if (gy0 + 0 >= vy0 && gy0 + 0 < vy1)
            *reinterpret_cast<float4*>(obase + (gy0 + 0) * IMG + gx) = a0;
        if (gy0 + 1 >= vy0 && gy0 + 1 < vy1)
            *reinterpret_cast<float4*>(obase + (gy0 + 1) * IMG + gx) = a1;
        if (gy0 + 2 >= vy0 && gy0 + 2 < vy1)
            *reinterpret_cast<float4*>(obase + (gy0 + 2) * IMG + gx) = a2;
        if (gy0 + 3 >= vy0 && gy0 + 3 < vy1)
            *reinterpret_cast<float4*>(obase + (gy0 + 3) * IMG + gx) = a3;
    }
}

// ---------------- uniqueness: bitmap scatter (reads g_buf[1]) ----------------
__global__ void __launch_bounds__(256) scatter_kernel() {
    int i = blockIdx.x * blockDim.x + threadIdx.x;   // float4 index, < NTOT/4
    float4 v = reinterpret_cast<const float4*>(g_buf[1])[i];
    unsigned* bmp = (i < (NTEN / 4)) ? g_bmp[0] : g_bmp[1];
    unsigned ids[4] = {(unsigned)v.x, (unsigned)v.y, (unsigned)v.z, (unsigned)v.w};
    unsigned prev = 0xffffffffu;
#pragma unroll
    for (int k = 0; k < 4; k++) {
        unsigned id = ids[k];
        if (id == prev) continue;                 // spatial dedup (labels cluster)
        prev = id;
        unsigned w = id >> 5, m = 1u << (id & 31);
        if (!(bmp[w] & m)) atomicOr(&bmp[w], m);  // test first: idempotent
    }
}

__global__ void __launch_bounds__(256) popcnt_kernel() {
    int which = blockIdx.y;
    int i = blockIdx.x * blockDim.x + threadIdx.x;
    int stride = gridDim.x * blockDim.x;
    int s = 0;
    for (int w = i; w < BMP_WORDS; w += stride) s += __popc(g_bmp[which][w]);
#pragma unroll
    for (int o = 16; o; o >>= 1) s += __shfl_down_sync(FULLMASK, s, o);
    __shared__ int sh[8];
    if ((threadIdx.x & 31) == 0) sh[threadIdx.x >> 5] = s;
    __syncthreads();
    if (threadIdx.x == 0) {
        int tot = 0;
        for (int w = 0; w < 8; w++) tot += sh[w];
        atomicAdd(&g_cnt[which], tot);
    }
}

// ---------------- epilogue ----------------
__global__ void final_kernel(float* __restrict__ out) {
    float acc = 0.f;
    for (int b = 0; b < NBATCH; b++) {
        float num = 0.f, den = 0.f;
        for (int c = 0; c < 32; c++) { num += g_pnum[b * 32 + c]; den += g_pden[b * 32 + c]; }
        acc += 1.0f - (num + 1.0f) / (den + 1.0f);
    }
    float nl = (float)(g_cnt[0] - 1);   // count_unique(labels) - 1
    float nt = (float)g_cnt[1];         // count_unique(target_number)
    float pen = sqrtf(nl / nt);
    if (!isfinite(pen)) pen = (float)NBATCH;
    pen = fminf(fmaxf(pen, 1.0f), (float)NBATCH);
    out[0] = (acc / (float)NBATCH) * pen;
}

// ---------------- launch ----------------
extern "C" void kernel_launch(void* const* d_in, const int* in_sizes, int n_in,
                              void* d_out, int out_size) {
    const float* p = (const float*)d_in[0];
    const float* t = (const float*)d_in[1];
    float* out = (float*)d_out;

    init_kernel<<<512, 256>>>();

    dim3 rgrid(32, 16);
    reduce_kernel<<<rgrid, 256>>>(p, t);

    seed_kernel<<<NTEN / 4 / 256, 256>>>(p, t);

    // 25 launches x 8 fused iterations = 200; ping-pong g_buf[0] <-> g_buf[1]
    dim3 pgrid(5, 11, 32);
    for (int it = 0; it < 25; ++it)
        prop8_kernel<<<pgrid, 512>>>(it & 1);     // final result lands in g_buf[1]

    scatter_kernel<<<NTOT / 4 / 256, 256>>>();

    dim3 cgrid(64, 2);
    popcnt_kernel<<<cgrid, 256>>>();

    final_kernel<<<1, 1>>>(out);
}